// round 3
// baseline (speedup 1.0000x reference)
#include <cuda_runtime.h>

// Problem constants
#define BT_TOK  65536       // B*T tokens
#define D_INV   512         // D_IN
#define D_EMBV  256         // D_EMB
#define K_CODES 1024
#define N_BATCH 16
#define T_SEQ   4096

// Scratch (device globals: no allocation allowed)
__device__ int   g_code[BT_TOK];
__device__ float g_c2[K_CODES];
__device__ float g_loss[N_BATCH];

// ---------------- packed f32x2 helpers (Blackwell dual fp32 pipe) ----------
static __device__ __forceinline__ unsigned long long bcast2(float x) {
    unsigned long long r;
    asm("mov.b64 %0, {%1, %1};" : "=l"(r) : "f"(x));
    return r;
}
static __device__ __forceinline__ void fma2(unsigned long long& c,
                                            unsigned long long a,
                                            unsigned long long b) {
    asm("fma.rn.f32x2 %0, %1, %2, %0;" : "+l"(c) : "l"(a), "l"(b));
}
static __device__ __forceinline__ float2 unpack2(unsigned long long v) {
    float2 f;
    f.x = __uint_as_float((unsigned)(v & 0xffffffffull));
    f.y = __uint_as_float((unsigned)(v >> 32));
    return f;
}

// ---------------- codebook squared norms ------------------------------------
__global__ void k_c2(const float* __restrict__ CB) {
    int k = blockIdx.x * blockDim.x + threadIdx.x;
    if (k < K_CODES) {
        const float* row = CB + k * D_EMBV;
        float s = 0.f;
        #pragma unroll 8
        for (int e = 0; e < D_EMBV; e++) s += row[e] * row[e];
        g_c2[k] = s;
    }
}

__global__ void k_zero() {
    if (threadIdx.x < N_BATCH) g_loss[threadIdx.x] = 0.f;
}

// ---------------- GEMM1: z_e_down = z_e @ W_down^T ---------------------------
// C[BT,256] = A[BT,512] * W[256,512]^T. 64x64x32 tile, 256 thr, 4x4 micro.
__global__ void k_down(const float* __restrict__ A, const float* __restrict__ W,
                       float* __restrict__ C) {
    __shared__ __align__(16) float As[32][68];
    __shared__ __align__(16) float Bs[32][68];
    const int m0 = blockIdx.x * 64;
    const int n0 = blockIdx.y * 64;
    const int tid = threadIdx.x;
    const int tx = tid & 15, ty = tid >> 4;
    unsigned long long acc[4][2];
    #pragma unroll
    for (int i = 0; i < 4; i++) { acc[i][0] = 0ull; acc[i][1] = 0ull; }

    for (int kk = 0; kk < D_INV; kk += 32) {
        #pragma unroll
        for (int i = 0; i < 8; i++) {
            int idx = tid + i * 256;
            int r = idx >> 5, c = idx & 31;
            As[c][r] = A[(m0 + r) * D_INV + kk + c];
            Bs[c][r] = W[(n0 + r) * D_INV + kk + c];
        }
        __syncthreads();
        #pragma unroll
        for (int k = 0; k < 32; k++) {
            float4 av = *(const float4*)&As[k][ty * 4];
            ulonglong2 bv = *(const ulonglong2*)&Bs[k][tx * 4];
            unsigned long long a0 = bcast2(av.x), a1 = bcast2(av.y);
            unsigned long long a2 = bcast2(av.z), a3 = bcast2(av.w);
            fma2(acc[0][0], a0, bv.x); fma2(acc[0][1], a0, bv.y);
            fma2(acc[1][0], a1, bv.x); fma2(acc[1][1], a1, bv.y);
            fma2(acc[2][0], a2, bv.x); fma2(acc[2][1], a2, bv.y);
            fma2(acc[3][0], a3, bv.x); fma2(acc[3][1], a3, bv.y);
        }
        __syncthreads();
    }
    #pragma unroll
    for (int i = 0; i < 4; i++) {
        float2 p0 = unpack2(acc[i][0]), p1 = unpack2(acc[i][1]);
        float4 o = make_float4(p0.x, p0.y, p1.x, p1.y);
        *(float4*)&C[(m0 + ty * 4 + i) * D_EMBV + n0 + tx * 4] = o;
    }
}

// ---------------- distance GEMM + fused argmin --------------------------------
// For each token t: code[t] = argmin_k ( c2[k] - 2 * dot(zed[t], CB[k]) ).
// One block owns 64 tokens and loops over all 1024 codes.
__global__ void k_dist(const float* __restrict__ Z, const float* __restrict__ CB,
                       float* __restrict__ code_f) {
    __shared__ __align__(16) float As[32][68];
    __shared__ __align__(16) float Bs[32][68];
    __shared__ float rv[64][17];
    __shared__ int   ri[64][17];
    const int m0 = blockIdx.x * 64;
    const int tid = threadIdx.x;
    const int tx = tid & 15, ty = tid >> 4;

    float minv[4]; int mini[4];
    #pragma unroll
    for (int i = 0; i < 4; i++) { minv[i] = 3.4e38f; mini[i] = 0; }

    for (int nc = 0; nc < K_CODES / 64; nc++) {
        unsigned long long acc[4][2];
        #pragma unroll
        for (int i = 0; i < 4; i++) { acc[i][0] = 0ull; acc[i][1] = 0ull; }

        for (int kc = 0; kc < D_EMBV / 32; kc++) {
            #pragma unroll
            for (int i = 0; i < 8; i++) {
                int idx = tid + i * 256;
                int r = idx >> 5, c = idx & 31;
                As[c][r] = Z[(m0 + r) * D_EMBV + kc * 32 + c];
                Bs[c][r] = CB[(nc * 64 + r) * D_EMBV + kc * 32 + c];
            }
            __syncthreads();
            #pragma unroll
            for (int k = 0; k < 32; k++) {
                float4 av = *(const float4*)&As[k][ty * 4];
                ulonglong2 bv = *(const ulonglong2*)&Bs[k][tx * 4];
                unsigned long long a0 = bcast2(av.x), a1 = bcast2(av.y);
                unsigned long long a2 = bcast2(av.z), a3 = bcast2(av.w);
                fma2(acc[0][0], a0, bv.x); fma2(acc[0][1], a0, bv.y);
                fma2(acc[1][0], a1, bv.x); fma2(acc[1][1], a1, bv.y);
                fma2(acc[2][0], a2, bv.x); fma2(acc[2][1], a2, bv.y);
                fma2(acc[3][0], a3, bv.x); fma2(acc[3][1], a3, bv.y);
            }
            __syncthreads();
        }
        // distances for this 64-code chunk; update running min (first-index ties)
        int kb = nc * 64 + tx * 4;
        float4 cv = *(const float4*)&g_c2[kb];
        #pragma unroll
        for (int i = 0; i < 4; i++) {
            float2 p0 = unpack2(acc[i][0]), p1 = unpack2(acc[i][1]);
            float d0 = cv.x - 2.f * p0.x;
            float d1 = cv.y - 2.f * p0.y;
            float d2 = cv.z - 2.f * p1.x;
            float d3 = cv.w - 2.f * p1.y;
            if (d0 < minv[i]) { minv[i] = d0; mini[i] = kb;     }
            if (d1 < minv[i]) { minv[i] = d1; mini[i] = kb + 1; }
            if (d2 < minv[i]) { minv[i] = d2; mini[i] = kb + 2; }
            if (d3 < minv[i]) { minv[i] = d3; mini[i] = kb + 3; }
        }
    }
    #pragma unroll
    for (int i = 0; i < 4; i++) {
        rv[ty * 4 + i][tx] = minv[i];
        ri[ty * 4 + i][tx] = mini[i];
    }
    __syncthreads();
    if (tid < 64) {
        float bv = rv[tid][0]; int bi = ri[tid][0];
        #pragma unroll
        for (int x = 1; x < 16; x++) {
            float v = rv[tid][x]; int ix = ri[tid][x];
            if (v < bv || (v == bv && ix < bi)) { bv = v; bi = ix; }
        }
        g_code[m0 + tid] = bi;
        code_f[m0 + tid] = (float)bi;
    }
}

// ---------------- GEMM3: z_q = codebook[code] @ W_up^T -----------------------
// C[BT,512] : C[t,d] = sum_e CB[code[t],e] * Wup[d,e]
__global__ void k_up(const float* __restrict__ CB, const float* __restrict__ W,
                     float* __restrict__ C) {
    __shared__ __align__(16) float As[32][68];
    __shared__ __align__(16) float Bs[32][68];
    __shared__ int codes[64];
    const int m0 = blockIdx.x * 64;
    const int n0 = blockIdx.y * 64;
    const int tid = threadIdx.x;
    const int tx = tid & 15, ty = tid >> 4;
    if (tid < 64) codes[tid] = g_code[m0 + tid];
    __syncthreads();

    unsigned long long acc[4][2];
    #pragma unroll
    for (int i = 0; i < 4; i++) { acc[i][0] = 0ull; acc[i][1] = 0ull; }

    for (int kk = 0; kk < D_EMBV; kk += 32) {
        #pragma unroll
        for (int i = 0; i < 8; i++) {
            int idx = tid + i * 256;
            int r = idx >> 5, c = idx & 31;
            As[c][r] = CB[codes[r] * D_EMBV + kk + c];
            Bs[c][r] = W[(n0 + r) * D_EMBV + kk + c];
        }
        __syncthreads();
        #pragma unroll
        for (int k = 0; k < 32; k++) {
            float4 av = *(const float4*)&As[k][ty * 4];
            ulonglong2 bv = *(const ulonglong2*)&Bs[k][tx * 4];
            unsigned long long a0 = bcast2(av.x), a1 = bcast2(av.y);
            unsigned long long a2 = bcast2(av.z), a3 = bcast2(av.w);
            fma2(acc[0][0], a0, bv.x); fma2(acc[0][1], a0, bv.y);
            fma2(acc[1][0], a1, bv.x); fma2(acc[1][1], a1, bv.y);
            fma2(acc[2][0], a2, bv.x); fma2(acc[2][1], a2, bv.y);
            fma2(acc[3][0], a3, bv.x); fma2(acc[3][1], a3, bv.y);
        }
        __syncthreads();
    }
    #pragma unroll
    for (int i = 0; i < 4; i++) {
        float2 p0 = unpack2(acc[i][0]), p1 = unpack2(acc[i][1]);
        float4 o = make_float4(p0.x, p0.y, p1.x, p1.y);
        *(float4*)&C[(m0 + ty * 4 + i) * D_INV + n0 + tx * 4] = o;
    }
}

// ---------------- per-batch VQ losses ---------------------------------------
// sum over (t,e) of (CB[code[t],e] - zed[t,e])^2, one warp per token.
__global__ void k_loss(const float* __restrict__ Z, const float* __restrict__ CB) {
    int lane = threadIdx.x & 31;
    int t = (blockIdx.x * blockDim.x + threadIdx.x) >> 5;
    int code = g_code[t];
    float s = 0.f;
    #pragma unroll
    for (int i = 0; i < 8; i++) {
        int e = lane + 32 * i;
        float d = Z[t * D_EMBV + e] - CB[code * D_EMBV + e];
        s += d * d;
    }
    #pragma unroll
    for (int o = 16; o > 0; o >>= 1) s += __shfl_xor_sync(0xffffffffu, s, o);
    if (lane == 0) atomicAdd(&g_loss[t >> 12], s);
}

__global__ void k_finish(float* __restrict__ out_commit, float* __restrict__ out_cb) {
    int i = threadIdx.x;
    if (i < N_BATCH) {
        float v = g_loss[i] * (1.0f / ((float)T_SEQ * (float)D_EMBV));
        out_commit[i] = v;
        out_cb[i] = v;
    }
}

// ---------------- launcher ----------------------------------------------------
extern "C" void kernel_launch(void* const* d_in, const int* in_sizes, int n_in,
                              void* d_out, int out_size) {
    const float* z_e    = (const float*)d_in[0];
    const float* cb     = (const float*)d_in[1];
    const float* w_down = (const float*)d_in[2];
    const float* w_up   = (const float*)d_in[3];

    float* out     = (float*)d_out;
    float* zq      = out;                                        // [BT, 512]
    float* zed     = out + (size_t)BT_TOK * D_INV;               // [BT, 256]
    float* codef   = out + (size_t)BT_TOK * (D_INV + D_EMBV);    // [BT]
    float* lcommit = codef + BT_TOK;                             // [16]
    float* lcb     = lcommit + N_BATCH;                          // [16]

    k_c2<<<(K_CODES + 255) / 256, 256>>>(cb);
    k_zero<<<1, 32>>>();
    k_down<<<dim3(BT_TOK / 64, D_EMBV / 64), 256>>>(z_e, w_down, zed);
    k_dist<<<BT_TOK / 64, 256>>>(zed, cb, codef);
    k_loss<<<BT_TOK / 8, 256>>>(zed, cb);
    k_up<<<dim3(BT_TOK / 64, D_INV / 64), 256>>>(cb, w_up, zq);
    k_finish<<<1, 32>>>(lcommit, lcb);
}

// round 5
// speedup vs baseline: 1.6821x; 1.6821x over previous
#include <cuda_runtime.h>
#include <cuda_bf16.h>

#define BT_TOK  65536
#define D_INV   512
#define D_EMBV  256
#define K_CODES 1024
#define N_BATCH 16
#define T_SEQ   4096

// ---------------- device scratch ---------------------------------------------
__device__ int           g_code[BT_TOK];
__device__ int           g_flag[BT_TOK];
__device__ float         g_c2[K_CODES];
__device__ float         g_loss[N_BATCH];
__device__ __nv_bfloat16 g_wd_h[D_EMBV * D_INV];
__device__ __nv_bfloat16 g_wd_m[D_EMBV * D_INV];
__device__ __nv_bfloat16 g_wd_l[D_EMBV * D_INV];
__device__ __nv_bfloat16 g_cb_h[K_CODES * D_EMBV];
__device__ __nv_bfloat16 g_cb_l[K_CODES * D_EMBV];
__device__ float         g_cbup[K_CODES * D_INV];

// ---------------- helpers -------------------------------------------------------
static __device__ __forceinline__ unsigned smem_u32(const void* p) {
    unsigned a;
    asm("{ .reg .u64 t; cvta.to.shared.u64 t, %1; cvt.u32.u64 %0, t; }"
        : "=r"(a) : "l"(p));
    return a;
}

#define LDSM4(d, addr) \
    asm volatile("ldmatrix.sync.aligned.m8n8.x4.shared.b16 {%0,%1,%2,%3}, [%4];" \
        : "=r"((d)[0]), "=r"((d)[1]), "=r"((d)[2]), "=r"((d)[3]) : "r"(addr))

#define LDSM4B(b0, b1, addr) \
    asm volatile("ldmatrix.sync.aligned.m8n8.x4.shared.b16 {%0,%1,%2,%3}, [%4];" \
        : "=r"((b0)[0]), "=r"((b0)[1]), "=r"((b1)[0]), "=r"((b1)[1]) : "r"(addr))

#define MMA_B16(c, a, b) \
    asm volatile("mma.sync.aligned.m16n8k16.row.col.f32.bf16.bf16.f32 " \
        "{%0,%1,%2,%3},{%4,%5,%6,%7},{%8,%9},{%0,%1,%2,%3};" \
        : "+f"((c)[0]), "+f"((c)[1]), "+f"((c)[2]), "+f"((c)[3]) \
        : "r"((a)[0]), "r"((a)[1]), "r"((a)[2]), "r"((a)[3]), "r"((b)[0]), "r"((b)[1]))

static __device__ __forceinline__ unsigned pack_bf2(float x, float y) {
    __nv_bfloat162 t = __float22bfloat162_rn(make_float2(x, y));
    return *(unsigned*)&t;
}

// 2-way split: v -> hi, lo  (each uint2 = 4 bf16)
static __device__ __forceinline__ void split2_f4(float4 v, uint2& h, uint2& l) {
    __nv_bfloat162 h01 = __float22bfloat162_rn(make_float2(v.x, v.y));
    __nv_bfloat162 h23 = __float22bfloat162_rn(make_float2(v.z, v.w));
    float r0 = v.x - __bfloat162float(h01.x);
    float r1 = v.y - __bfloat162float(h01.y);
    float r2 = v.z - __bfloat162float(h23.x);
    float r3 = v.w - __bfloat162float(h23.y);
    h.x = *(unsigned*)&h01; h.y = *(unsigned*)&h23;
    l.x = pack_bf2(r0, r1); l.y = pack_bf2(r2, r3);
}

// 3-way split: v -> h, m, l
static __device__ __forceinline__ void split3_f4(float4 v, uint2& h, uint2& m, uint2& l) {
    float hf[4], mf[4], lf[4];
    float in[4] = {v.x, v.y, v.z, v.w};
    #pragma unroll
    for (int i = 0; i < 4; i++) {
        __nv_bfloat16 hb = __float2bfloat16(in[i]);
        float r = in[i] - __bfloat162float(hb);
        __nv_bfloat16 mb = __float2bfloat16(r);
        float r2 = r - __bfloat162float(mb);
        hf[i] = __bfloat162float(hb);
        mf[i] = __bfloat162float(mb);
        lf[i] = r2;
    }
    h.x = pack_bf2(hf[0], hf[1]); h.y = pack_bf2(hf[2], hf[3]);
    m.x = pack_bf2(mf[0], mf[1]); m.y = pack_bf2(mf[2], mf[3]);
    l.x = pack_bf2(lf[0], lf[1]); l.y = pack_bf2(lf[2], lf[3]);
}

// ---------------- prep kernels ---------------------------------------------------
__global__ void k_prep(const float* __restrict__ wd, const float* __restrict__ cb) {
    int i = blockIdx.x * blockDim.x + threadIdx.x;
    if (i < D_EMBV * D_INV) {
        float x = wd[i];
        __nv_bfloat16 h = __float2bfloat16(x);
        float r = x - __bfloat162float(h);
        __nv_bfloat16 m = __float2bfloat16(r);
        g_wd_h[i] = h;
        g_wd_m[i] = m;
        g_wd_l[i] = __float2bfloat16(r - __bfloat162float(m));
    }
    int j = i - D_EMBV * D_INV;
    if (j >= 0 && j < K_CODES * D_EMBV) {
        float x = cb[j];
        __nv_bfloat16 h = __float2bfloat16(x);
        g_cb_h[j] = h;
        g_cb_l[j] = __float2bfloat16(x - __bfloat162float(h));
    }
}
__global__ void k_c2(const float* __restrict__ CB) {
    int k = blockIdx.x * blockDim.x + threadIdx.x;
    if (k < K_CODES) {
        const float* row = CB + (size_t)k * D_EMBV;
        float s = 0.f;
        #pragma unroll 8
        for (int e = 0; e < D_EMBV; e++) s += row[e] * row[e];
        g_c2[k] = s;
    }
}
__global__ void k_zero() { if (threadIdx.x < N_BATCH) g_loss[threadIdx.x] = 0.f; }

// ---------------- CBup = codebook @ W_up^T (small fp32 SIMT GEMM) ----------------
static __device__ __forceinline__ unsigned long long bcast2(float x) {
    unsigned long long r; asm("mov.b64 %0, {%1, %1};" : "=l"(r) : "f"(x)); return r;
}
static __device__ __forceinline__ void fma2(unsigned long long& c, unsigned long long a,
                                            unsigned long long b) {
    asm("fma.rn.f32x2 %0, %1, %2, %0;" : "+l"(c) : "l"(a), "l"(b));
}
static __device__ __forceinline__ float2 unpack2(unsigned long long v) {
    float2 f;
    f.x = __uint_as_float((unsigned)(v & 0xffffffffull));
    f.y = __uint_as_float((unsigned)(v >> 32));
    return f;
}
__global__ void k_cbup(const float* __restrict__ A, const float* __restrict__ W) {
    __shared__ __align__(16) float As[32][68];
    __shared__ __align__(16) float Bs[32][68];
    const int m0 = blockIdx.x * 64, n0 = blockIdx.y * 64;
    const int tid = threadIdx.x, tx = tid & 15, ty = tid >> 4;
    unsigned long long acc[4][2];
    #pragma unroll
    for (int i = 0; i < 4; i++) { acc[i][0] = 0ull; acc[i][1] = 0ull; }
    for (int kk = 0; kk < D_EMBV; kk += 32) {
        #pragma unroll
        for (int i = 0; i < 8; i++) {
            int idx = tid + i * 256, r = idx >> 5, c = idx & 31;
            As[c][r] = A[(size_t)(m0 + r) * D_EMBV + kk + c];
            Bs[c][r] = W[(size_t)(n0 + r) * D_EMBV + kk + c];
        }
        __syncthreads();
        #pragma unroll
        for (int k = 0; k < 32; k++) {
            float4 av = *(const float4*)&As[k][ty * 4];
            ulonglong2 bv = *(const ulonglong2*)&Bs[k][tx * 4];
            unsigned long long a0 = bcast2(av.x), a1 = bcast2(av.y);
            unsigned long long a2 = bcast2(av.z), a3 = bcast2(av.w);
            fma2(acc[0][0], a0, bv.x); fma2(acc[0][1], a0, bv.y);
            fma2(acc[1][0], a1, bv.x); fma2(acc[1][1], a1, bv.y);
            fma2(acc[2][0], a2, bv.x); fma2(acc[2][1], a2, bv.y);
            fma2(acc[3][0], a3, bv.x); fma2(acc[3][1], a3, bv.y);
        }
        __syncthreads();
    }
    #pragma unroll
    for (int i = 0; i < 4; i++) {
        float2 p0 = unpack2(acc[i][0]), p1 = unpack2(acc[i][1]);
        *(float4*)&g_cbup[(size_t)(m0 + ty * 4 + i) * D_INV + n0 + tx * 4] =
            make_float4(p0.x, p0.y, p1.x, p1.y);
    }
}

// ---------------- k_down: zed = z_e @ Wd^T  (bf16 3-split, 5-pass HMMA) ----------
// smem per buffer (61440B): Ah@0 Am@10240 Al@20480 Bh@30720 Bm@40960 Bl@51200
// two buffers -> 122880B dynamic. Rows padded to 80B (40 halves).
#define DN_BUF   61440
#define DN_SMEM  122880
__global__ void __launch_bounds__(256, 1) k_down(const float* __restrict__ A,
                                                 float* __restrict__ C) {
    extern __shared__ __align__(16) char sm[];
    const unsigned sb = smem_u32(sm);
    const int tid = threadIdx.x, lane = tid & 31, wid = tid >> 5;
    const int wr = wid >> 1, wc = wid & 1;
    const int m0 = blockIdx.x * 128, n0 = blockIdx.y * 128;

    float acc[2][8][4];
    #pragma unroll
    for (int mi = 0; mi < 2; mi++)
        #pragma unroll
        for (int ni = 0; ni < 8; ni++)
            #pragma unroll
            for (int q = 0; q < 4; q++) acc[mi][ni][q] = 0.f;

    float4 areg[4];
    uint4  bh[2], bm[2], bl[2];

    // prefetch chunk 0
    #pragma unroll
    for (int i = 0; i < 4; i++) {
        int j = tid + i * 256, r = j >> 3, c4 = j & 7;
        areg[i] = *(const float4*)&A[(size_t)(m0 + r) * D_INV + c4 * 4];
    }
    #pragma unroll
    for (int i = 0; i < 2; i++) {
        int j = tid + i * 256, r = j >> 2, c = j & 3;
        size_t src = (size_t)(n0 + r) * D_INV + c * 8;
        bh[i] = *(const uint4*)&g_wd_h[src];
        bm[i] = *(const uint4*)&g_wd_m[src];
        bl[i] = *(const uint4*)&g_wd_l[src];
    }
    // store chunk 0
    {
        char* base = sm;
        #pragma unroll
        for (int i = 0; i < 4; i++) {
            int j = tid + i * 256, r = j >> 3, c4 = j & 7;
            uint2 h, m, l; split3_f4(areg[i], h, m, l);
            unsigned off = r * 80 + c4 * 8;
            *(uint2*)(base + off) = h;
            *(uint2*)(base + 10240 + off) = m;
            *(uint2*)(base + 20480 + off) = l;
        }
        #pragma unroll
        for (int i = 0; i < 2; i++) {
            int j = tid + i * 256, r = j >> 2, c = j & 3;
            unsigned off = r * 80 + c * 16;
            *(uint4*)(base + 30720 + off) = bh[i];
            *(uint4*)(base + 40960 + off) = bm[i];
            *(uint4*)(base + 51200 + off) = bl[i];
        }
    }
    __syncthreads();

    #pragma unroll 1
    for (int ch = 0; ch < 16; ch++) {
        int nxt = ch + 1;
        if (nxt < 16) {
            #pragma unroll
            for (int i = 0; i < 4; i++) {
                int j = tid + i * 256, r = j >> 3, c4 = j & 7;
                areg[i] = *(const float4*)&A[(size_t)(m0 + r) * D_INV + nxt * 32 + c4 * 4];
            }
            #pragma unroll
            for (int i = 0; i < 2; i++) {
                int j = tid + i * 256, r = j >> 2, c = j & 3;
                size_t src = (size_t)(n0 + r) * D_INV + nxt * 32 + c * 8;
                bh[i] = *(const uint4*)&g_wd_h[src];
                bm[i] = *(const uint4*)&g_wd_m[src];
                bl[i] = *(const uint4*)&g_wd_l[src];
            }
        }
        // MMA on buffer ch&1
        {
            unsigned bufb = sb + (ch & 1) * DN_BUF;
            #pragma unroll
            for (int s = 0; s < 2; s++) {
                unsigned a_h[2][4], a_m[2][4], a_l[2][4];
                #pragma unroll
                for (int mi = 0; mi < 2; mi++) {
                    unsigned off = (wr * 32 + mi * 16 + (lane & 15)) * 80 +
                                   ((lane >> 4) << 4) + s * 32;
                    LDSM4(a_h[mi], bufb + off);
                    LDSM4(a_m[mi], bufb + 10240 + off);
                    LDSM4(a_l[mi], bufb + 20480 + off);
                }
                #pragma unroll
                for (int nh = 0; nh < 2; nh++) {
                    unsigned b_h[4][2], b_m[4][2], b_l[4][2];
                    #pragma unroll
                    for (int p = 0; p < 2; p++) {
                        int np = nh * 2 + p;
                        unsigned off = (wc * 64 + np * 16 + (lane & 7) +
                                        ((lane >> 4) << 3)) * 80 +
                                       (((lane >> 3) & 1) << 4) + s * 32;
                        LDSM4B(b_h[p * 2], b_h[p * 2 + 1], bufb + 30720 + off);
                        LDSM4B(b_m[p * 2], b_m[p * 2 + 1], bufb + 40960 + off);
                        LDSM4B(b_l[p * 2], b_l[p * 2 + 1], bufb + 51200 + off);
                    }
                    #pragma unroll
                    for (int mi = 0; mi < 2; mi++)
                        #pragma unroll
                        for (int k = 0; k < 4; k++) {
                            float* c = acc[mi][nh * 4 + k];
                            MMA_B16(c, a_h[mi], b_h[k]);
                            MMA_B16(c, a_h[mi], b_m[k]);
                            MMA_B16(c, a_m[mi], b_h[k]);
                            MMA_B16(c, a_h[mi], b_l[k]);
                            MMA_B16(c, a_l[mi], b_h[k]);
                        }
                }
            }
        }
        // store next chunk
        if (nxt < 16) {
            char* base = sm + (nxt & 1) * DN_BUF;
            #pragma unroll
            for (int i = 0; i < 4; i++) {
                int j = tid + i * 256, r = j >> 3, c4 = j & 7;
                uint2 h, m, l; split3_f4(areg[i], h, m, l);
                unsigned off = r * 80 + c4 * 8;
                *(uint2*)(base + off) = h;
                *(uint2*)(base + 10240 + off) = m;
                *(uint2*)(base + 20480 + off) = l;
            }
            #pragma unroll
            for (int i = 0; i < 2; i++) {
                int j = tid + i * 256, r = j >> 2, c = j & 3;
                unsigned off = r * 80 + c * 16;
                *(uint4*)(base + 30720 + off) = bh[i];
                *(uint4*)(base + 40960 + off) = bm[i];
                *(uint4*)(base + 51200 + off) = bl[i];
            }
        }
        __syncthreads();
    }
    // epilogue
    #pragma unroll
    for (int mi = 0; mi < 2; mi++)
        #pragma unroll
        for (int h = 0; h < 2; h++) {
            int row = m0 + wr * 32 + mi * 16 + h * 8 + (lane >> 2);
            #pragma unroll
            for (int ni = 0; ni < 8; ni++) {
                int col = n0 + wc * 64 + ni * 8 + 2 * (lane & 3);
                *(float2*)&C[(size_t)row * D_EMBV + col] =
                    make_float2(acc[mi][ni][h * 2], acc[mi][ni][h * 2 + 1]);
            }
        }
}

// ---------------- k_dist: fused dist GEMM + top2 argmin (bf16 2-split, 3-pass) ---
// smem: Ah chunks 0..7 @0 (8*10240) | Al @81920 | B bufs @163840 (2 * 20480)
// reduction @204800: m1(1024B) i1(1024B) m2(1024B) -> total 207872
#define DS_AL   81920
#define DS_BB   163840
#define DS_RED  204800
#define DS_SMEM 207872
__global__ void __launch_bounds__(256, 1) k_dist(const float* __restrict__ Z,
                                                 float* __restrict__ code_f) {
    extern __shared__ __align__(16) char sm[];
    const unsigned sb = smem_u32(sm);
    const int tid = threadIdx.x, lane = tid & 31, wid = tid >> 5;
    const int wr = wid >> 1, wc = wid & 1;
    const int m0 = blockIdx.x * 128;

    // resident A: split zed[m0..+128, 0..256) into 8 chunk tiles (hi/lo)
    #pragma unroll 4
    for (int i = 0; i < 32; i++) {
        int j = tid + i * 256, r = j >> 6, col4 = j & 63;
        int ch = col4 >> 3, c4 = col4 & 7;
        float4 v = *(const float4*)&Z[(size_t)(m0 + r) * D_EMBV + col4 * 4];
        uint2 h, l; split2_f4(v, h, l);
        unsigned off = ch * 10240 + r * 80 + c4 * 8;
        *(uint2*)(sm + off) = h;
        *(uint2*)(sm + DS_AL + off) = l;
    }

    float acc[2][8][4];
    #pragma unroll
    for (int mi = 0; mi < 2; mi++)
        #pragma unroll
        for (int ni = 0; ni < 8; ni++)
            #pragma unroll
            for (int q = 0; q < 4; q++) acc[mi][ni][q] = 0.f;

    float t1[4], t2[4]; int ti[4];
    #pragma unroll
    for (int s = 0; s < 4; s++) { t1[s] = 3.4e38f; t2[s] = 3.4e38f; ti[s] = 0; }

    uint4 pbh[2], pbl[2];
    // prefetch it=0  (nt=0, ch=0)
    #pragma unroll
    for (int i = 0; i < 2; i++) {
        int j = tid + i * 256, r = j >> 2, c = j & 3;
        size_t src = (size_t)r * D_EMBV + c * 8;
        pbh[i] = *(const uint4*)&g_cb_h[src];
        pbl[i] = *(const uint4*)&g_cb_l[src];
    }
    {
        char* base = sm + DS_BB;
        #pragma unroll
        for (int i = 0; i < 2; i++) {
            int j = tid + i * 256, r = j >> 2, c = j & 3;
            unsigned off = r * 80 + c * 16;
            *(uint4*)(base + off) = pbh[i];
            *(uint4*)(base + 10240 + off) = pbl[i];
        }
    }
    __syncthreads();

    #pragma unroll 1
    for (int it = 0; it < 64; it++) {
        int nt = it >> 3, ch = it & 7;
        int nxt = it + 1;
        if (nxt < 64) {
            int nnt = nxt >> 3, nch = nxt & 7;
            #pragma unroll
            for (int i = 0; i < 2; i++) {
                int j = tid + i * 256, r = j >> 2, c = j & 3;
                size_t src = (size_t)(nnt * 128 + r) * D_EMBV + nch * 32 + c * 8;
                pbh[i] = *(const uint4*)&g_cb_h[src];
                pbl[i] = *(const uint4*)&g_cb_l[src];
            }
        }
        // MMA: A chunk tile ch (resident) x B buffer it&1
        {
            unsigned abase = sb + ch * 10240;
            unsigned bbase = sb + DS_BB + (it & 1) * 20480;
            #pragma unroll
            for (int s = 0; s < 2; s++) {
                unsigned a_h[2][4], a_l[2][4];
                #pragma unroll
                for (int mi = 0; mi < 2; mi++) {
                    unsigned off = (wr * 32 + mi * 16 + (lane & 15)) * 80 +
                                   ((lane >> 4) << 4) + s * 32;
                    LDSM4(a_h[mi], abase + off);
                    LDSM4(a_l[mi], abase + DS_AL + off);
                }
                #pragma unroll
                for (int nh = 0; nh < 2; nh++) {
                    unsigned b_h[4][2], b_l[4][2];
                    #pragma unroll
                    for (int p = 0; p < 2; p++) {
                        int np = nh * 2 + p;
                        unsigned off = (wc * 64 + np * 16 + (lane & 7) +
                                        ((lane >> 4) << 3)) * 80 +
                                       (((lane >> 3) & 1) << 4) + s * 32;
                        LDSM4B(b_h[p * 2], b_h[p * 2 + 1], bbase + off);
                        LDSM4B(b_l[p * 2], b_l[p * 2 + 1], bbase + 10240 + off);
                    }
                    #pragma unroll
                    for (int mi = 0; mi < 2; mi++)
                        #pragma unroll
                        for (int k = 0; k < 4; k++) {
                            float* c = acc[mi][nh * 4 + k];
                            MMA_B16(c, a_h[mi], b_h[k]);
                            MMA_B16(c, a_l[mi], b_h[k]);
                            MMA_B16(c, a_h[mi], b_l[k]);
                        }
                }
            }
        }
        // end of N-tile: fold distances into running top-2
        if (ch == 7) {
            #pragma unroll
            for (int ni = 0; ni < 8; ni++)
                #pragma unroll
                for (int cc = 0; cc < 2; cc++) {
                    int g = nt * 128 + wc * 64 + ni * 8 + 2 * (lane & 3) + cc;
                    float c2v = __ldg(&g_c2[g]);
                    #pragma unroll
                    for (int mi = 0; mi < 2; mi++)
                        #pragma unroll
                        for (int h = 0; h < 2; h++) {
                            int slot = mi * 2 + h;
                            float d = c2v - 2.f * acc[mi][ni][h * 2 + cc];
                            if (d < t1[slot]) { t2[slot] = t1[slot]; t1[slot] = d; ti[slot] = g; }
                            else if (d < t2[slot]) { t2[slot] = d; }
                        }
                }
            #pragma unroll
            for (int mi = 0; mi < 2; mi++)
                #pragma unroll
                for (int ni = 0; ni < 8; ni++)
                    #pragma unroll
                    for (int q = 0; q < 4; q++) acc[mi][ni][q] = 0.f;
        }
        // store next B buffer
        if (nxt < 64) {
            char* base = sm + DS_BB + (nxt & 1) * 20480;
            #pragma unroll
            for (int i = 0; i < 2; i++) {
                int j = tid + i * 256, r = j >> 2, c = j & 3;
                unsigned off = r * 80 + c * 16;
                *(uint4*)(base + off) = pbh[i];
                *(uint4*)(base + 10240 + off) = pbl[i];
            }
        }
        __syncthreads();
    }

    // quad reduce (lanes sharing lane>>2 hold the same rows)
    #pragma unroll
    for (int s = 0; s < 4; s++) {
        #pragma unroll
        for (int off = 1; off <= 2; off <<= 1) {
            float o1 = __shfl_xor_sync(0xffffffffu, t1[s], off);
            float o2 = __shfl_xor_sync(0xffffffffu, t2[s], off);
            int oi = __shfl_xor_sync(0xffffffffu, ti[s], off);
            bool takeo = (o1 < t1[s]) || (o1 == t1[s] && oi < ti[s]);
            float nm2 = takeo ? fminf(t1[s], o2) : fminf(t2[s], o1);
            if (takeo) { t1[s] = o1; ti[s] = oi; }
            t2[s] = nm2;
        }
    }
    float* red_m1 = (float*)(sm + DS_RED);
    int*   red_i1 = (int*)(sm + DS_RED + 1024);
    float* red_m2 = (float*)(sm + DS_RED + 2048);
    if ((lane & 3) == 0) {
        #pragma unroll
        for (int mi = 0; mi < 2; mi++)
            #pragma unroll
            for (int h = 0; h < 2; h++) {
                int s = mi * 2 + h;
                int row = wr * 32 + mi * 16 + h * 8 + (lane >> 2);
                red_m1[row * 2 + wc] = t1[s];
                red_i1[row * 2 + wc] = ti[s];
                red_m2[row * 2 + wc] = t2[s];
            }
    }
    __syncthreads();
    if (tid < 128) {
        float m1a = red_m1[tid * 2], m2a = red_m2[tid * 2];
        int   i1a = red_i1[tid * 2];
        float m1b = red_m1[tid * 2 + 1], m2b = red_m2[tid * 2 + 1];
        int   i1b = red_i1[tid * 2 + 1];
        bool takeb = (m1b < m1a) || (m1b == m1a && i1b < i1a);
        float m1c = takeb ? m1b : m1a;
        int   i1c = takeb ? i1b : i1a;
        float m2c = takeb ? fminf(m1a, m2b) : fminf(m2a, m1b);
        int t = m0 + tid;
        g_code[t] = i1c;
        code_f[t] = (float)i1c;
        g_flag[t] = (m2c - m1c < 0.02f) ? 1 : 0;
    }
}

// ---------------- exact fp32 re-check for ambiguous tokens -----------------------
__global__ void k_fix(const float* __restrict__ Z, const float* __restrict__ CB,
                      float* __restrict__ code_f) {
    int t = blockIdx.x * 8 + (threadIdx.x >> 5);
    int lane = threadIdx.x & 31;
    if (!g_flag[t]) return;
    const float* z = Z + (size_t)t * D_EMBV;
    float best = 3.4e38f; int bi = K_CODES;
    for (int kk = lane * 32; kk < lane * 32 + 32; kk++) {
        const float* cr = CB + (size_t)kk * D_EMBV;
        float dot = 0.f;
        #pragma unroll 8
        for (int e = 0; e < D_EMBV; e++) dot += z[e] * cr[e];
        float d = g_c2[kk] - 2.f * dot;
        if (d < best) { best = d; bi = kk; }
    }
    #pragma unroll
    for (int o = 16; o > 0; o >>= 1) {
        float od = __shfl_xor_sync(0xffffffffu, best, o);
        int oi = __shfl_xor_sync(0xffffffffu, bi, o);
        if (od < best || (od == best && oi < bi)) { best = od; bi = oi; }
    }
    if (lane == 0) { g_code[t] = bi; code_f[t] = (float)bi; }
}

// ---------------- gather: zq[t] = CBup[code[t]] ----------------------------------
__global__ void k_gather(float* __restrict__ ZQ) {
    int idx = blockIdx.x * blockDim.x + threadIdx.x;
    int t = idx >> 7, j = idx & 127;
    int code = g_code[t];
    ((float4*)ZQ)[(size_t)t * 128 + j] = ((const float4*)g_cbup)[(size_t)code * 128 + j];
}

// ---------------- per-batch VQ losses --------------------------------------------
__global__ void k_loss(const float* __restrict__ Z, const float* __restrict__ CB) {
    int lane = threadIdx.x & 31;
    int t = (blockIdx.x * blockDim.x + threadIdx.x) >> 5;
    int code = g_code[t];
    float s = 0.f;
    #pragma unroll
    for (int i = 0; i < 8; i++) {
        int e = lane + 32 * i;
        float d = Z[(size_t)t * D_EMBV + e] - CB[(size_t)code * D_EMBV + e];
        s += d * d;
    }
    #pragma unroll
    for (int o = 16; o > 0; o >>= 1) s += __shfl_xor_sync(0xffffffffu, s, o);
    if (lane == 0) atomicAdd(&g_loss[t >> 12], s);
}
__global__ void k_finish(float* __restrict__ oc, float* __restrict__ ob) {
    int i = threadIdx.x;
    if (i < N_BATCH) {
        float v = g_loss[i] * (1.0f / ((float)T_SEQ * (float)D_EMBV));
        oc[i] = v; ob[i] = v;
    }
}

// ---------------- launcher --------------------------------------------------------
extern "C" void kernel_launch(void* const* d_in, const int* in_sizes, int n_in,
                              void* d_out, int out_size) {
    const float* z_e    = (const float*)d_in[0];
    const float* cb     = (const float*)d_in[1];
    const float* w_down = (const float*)d_in[2];
    const float* w_up   = (const float*)d_in[3];

    float* out     = (float*)d_out;
    float* zq      = out;
    float* zed     = out + (size_t)BT_TOK * D_INV;
    float* codef   = out + (size_t)BT_TOK * (D_INV + D_EMBV);
    float* lcommit = codef + BT_TOK;
    float* lcb     = lcommit + N_BATCH;

    cudaFuncSetAttribute(k_down, cudaFuncAttributeMaxDynamicSharedMemorySize, DN_SMEM);
    cudaFuncSetAttribute(k_dist, cudaFuncAttributeMaxDynamicSharedMemorySize, DS_SMEM);

    k_prep<<<(D_EMBV * D_INV + K_CODES * D_EMBV + 255) / 256, 256>>>(w_down, cb);
    k_c2<<<(K_CODES + 255) / 256, 256>>>(cb);
    k_zero<<<1, 32>>>();
    k_cbup<<<dim3(K_CODES / 64, D_INV / 64), 256>>>(cb, w_up);
    k_down<<<dim3(BT_TOK / 128, 2), 256, DN_SMEM>>>(z_e, zed);
    k_dist<<<BT_TOK / 128, 256, DS_SMEM>>>(zed, codef);
    k_fix<<<BT_TOK / 8, 256>>>(zed, cb, codef);
    k_gather<<<(BT_TOK * 128) / 256, 256>>>(zq);
    k_loss<<<BT_TOK / 8, 256>>>(zed, cb);
    k_finish<<<1, 32>>>(lcommit, lcb);
}